// round 1
// baseline (speedup 1.0000x reference)
#include <cuda_runtime.h>

#define NN 8192
#define FF 256

// ---- device scratch (no allocations allowed) ----
__device__ __align__(16) float g_Y[NN * FF];   // scaled emb (Y = alpha * E)
__device__ __align__(16) float g_E[NN * FF];   // updated emb
__device__ __align__(16) float g_G[FF * FF];   // Gram matrix Y^T Y
__device__ __align__(16) float g_s[FF];        // colsum(Y)
__device__ __align__(16) float g_sf[FF];       // colsum(final E)
__device__ float g_r[NN];                      // per-row sumsq
__device__ float g_T;                          // total sumsq (Frobenius^2)
__device__ float g_ab[4];                      // a0,b0,a1,b1

// ---- K0: a_i = feat_i . linear_i, b_i = dirv_i . linear_i ----
__global__ void k_ab(const float* __restrict__ linear,
                     const float* __restrict__ dirv,
                     const float* __restrict__ feat) {
    __shared__ float red[256];
    int t = threadIdx.x;
    for (int i = 0; i < 2; i++) {
        float pa = feat[i * FF + t] * linear[i * FF + t];
        float pb = dirv[i * FF + t] * linear[i * FF + t];
        red[t] = pa; __syncthreads();
        for (int o = 128; o > 0; o >>= 1) { if (t < o) red[t] += red[t + o]; __syncthreads(); }
        if (t == 0) g_ab[2 * i] = red[0];
        __syncthreads();
        red[t] = pb; __syncthreads();
        for (int o = 128; o > 0; o >>= 1) { if (t < o) red[t] += red[t + o]; __syncthreads(); }
        if (t == 0) g_ab[2 * i + 1] = red[0];
        __syncthreads();
    }
}

// ---- zero selected accumulators. mode bits: 1=T, 2=G, 4=s, 8=sf ----
__global__ void k_zero(int mode) {
    int i = blockIdx.x * blockDim.x + threadIdx.x;
    if ((mode & 1) && i == 0) g_T = 0.f;
    if ((mode & 2) && i < FF * FF) g_G[i] = 0.f;
    if ((mode & 4) && i < FF) g_s[i] = 0.f;
    if ((mode & 8) && i < FF) g_sf[i] = 0.f;
}

// ---- K1: per-row sumsq of X, accumulate total ----
__global__ void k_rownorm(const float* __restrict__ X) {
    int warp = threadIdx.x >> 5, lane = threadIdx.x & 31;
    int row = blockIdx.x * 8 + warp;
    const float* xr = X + row * FF;
    float s = 0.f;
#pragma unroll
    for (int u = 0; u < 8; u++) { float v = xr[lane + 32 * u]; s += v * v; }
#pragma unroll
    for (int o = 16; o > 0; o >>= 1) s += __shfl_xor_sync(0xffffffffu, s, o);
    __shared__ float ws[8];
    if (lane == 0) { ws[warp] = s; g_r[row] = s; }
    __syncthreads();
    if (threadIdx.x == 0) {
        float tt = 0.f;
        for (int w = 0; w < 8; w++) tt += ws[w];
        atomicAdd(&g_T, tt);
    }
}

// ---- K2: Y = alpha_j * src,  s += colsum(Y) ----
__global__ void k_scale(const float* __restrict__ xin, int use_E, int iter) {
    const float* src = use_E ? g_E : xin;
    int t = threadIdx.x;
    int r0 = blockIdx.x * 32;
    float a = g_ab[2 * iter], b = g_ab[2 * iter + 1];
    float nf = sqrtf(g_T);
    float sb = (b >= 0.f) ? 1.f : -1.f;
    float cs = 0.f;
    for (int j = r0; j < r0 + 32; j++) {
        float rj = g_r[j];
        float inner = a * sb * rj / nf;
        float scale = (inner <= 0.f) ? inner : 0.f;
        float alpha = a - scale * sb / nf;
        float y = alpha * src[j * FF + t];
        g_Y[j * FF + t] = y;
        cs += y;
    }
    atomicAdd(&g_s[t], cs);
}

// ---- K4: G += Y^T Y (tiled 64x64, atomic reduce over row-chunks) ----
__global__ void k_syrk() {
    __shared__ __align__(16) float As[16][64];
    __shared__ __align__(16) float Bs[16][64];
    int t = threadIdx.x;
    int pa = blockIdx.x >> 2, pb = blockIdx.x & 3;
    int rowbase = blockIdx.y * 512;
    int tx = t & 15, ty = t >> 4;
    int lk = t >> 4;
    int lc = (t & 15) * 4;
    float acc[4][4];
#pragma unroll
    for (int i = 0; i < 4; i++)
#pragma unroll
        for (int j = 0; j < 4; j++) acc[i][j] = 0.f;

    for (int r0 = rowbase; r0 < rowbase + 512; r0 += 16) {
        __syncthreads();
        *(float4*)&As[lk][lc] = *(const float4*)&g_Y[(r0 + lk) * FF + pa * 64 + lc];
        *(float4*)&Bs[lk][lc] = *(const float4*)&g_Y[(r0 + lk) * FF + pb * 64 + lc];
        __syncthreads();
#pragma unroll
        for (int kk = 0; kk < 16; kk++) {
            float4 av = *(float4*)&As[kk][4 * tx];
            float4 bv = *(float4*)&Bs[kk][4 * ty];
            float aa[4] = {av.x, av.y, av.z, av.w};
            float bb[4] = {bv.x, bv.y, bv.z, bv.w};
#pragma unroll
            for (int i = 0; i < 4; i++)
#pragma unroll
                for (int j = 0; j < 4; j++) acc[i][j] += aa[i] * bb[j];
        }
    }
#pragma unroll
    for (int i = 0; i < 4; i++) {
        int gp = pa * 64 + 4 * tx + i;
#pragma unroll
        for (int j = 0; j < 4; j++)
            atomicAdd(&g_G[gp * FF + pb * 64 + 4 * ty + j], acc[i][j]);
    }
}

// ---- K5: E = Y + (Y G - (Y.s) Y)/N ; also r(E), T += ; optionally sf += colsum(E)
__global__ void k_update(int final_flag) {
    __shared__ __align__(16) float Ysh[16][FF];
    __shared__ float s_sh[FF];
    __shared__ float dsh[16];
    __shared__ float rsh[16];
    int t = threadIdx.x;
    int rowbase = blockIdx.x * 16;
    if (t < 16) rsh[t] = 0.f;
    s_sh[t] = g_s[t];
#pragma unroll
    for (int l = 0; l < 16; l++)
        Ysh[l][t] = g_Y[(rowbase + l) * FF + t];
    __syncthreads();

    int warp = t >> 5, lane = t & 31;
#pragma unroll
    for (int rr = 0; rr < 2; rr++) {
        int r = warp * 2 + rr;
        float d = 0.f;
#pragma unroll
        for (int u = 0; u < 8; u++) { int c = lane + 32 * u; d += Ysh[r][c] * s_sh[c]; }
#pragma unroll
        for (int o = 16; o > 0; o >>= 1) d += __shfl_xor_sync(0xffffffffu, d, o);
        if (lane == 0) dsh[r] = d;
    }
    __syncthreads();

    int c0 = (t & 63) * 4, slot = t >> 6;
    float acc[4][4];
#pragma unroll
    for (int i = 0; i < 4; i++)
#pragma unroll
        for (int j = 0; j < 4; j++) acc[i][j] = 0.f;

    for (int k = 0; k < FF; k++) {
        float4 gv = *(const float4*)&g_G[k * FF + c0];
#pragma unroll
        for (int r = 0; r < 4; r++) {
            float y = Ysh[slot * 4 + r][k];
            acc[r][0] += y * gv.x; acc[r][1] += y * gv.y;
            acc[r][2] += y * gv.z; acc[r][3] += y * gv.w;
        }
    }

    const float inv = 1.0f / NN;
    float cs[4] = {0.f, 0.f, 0.f, 0.f};
#pragma unroll
    for (int r = 0; r < 4; r++) {
        int row = slot * 4 + r;
        float d = dsh[row];
        float4 yv = *(float4*)&Ysh[row][c0];
        float4 ev;
        ev.x = yv.x + (acc[r][0] - d * yv.x) * inv;
        ev.y = yv.y + (acc[r][1] - d * yv.y) * inv;
        ev.z = yv.z + (acc[r][2] - d * yv.z) * inv;
        ev.w = yv.w + (acc[r][3] - d * yv.w) * inv;
        *(float4*)&g_E[(rowbase + row) * FF + c0] = ev;
        float rq = ev.x * ev.x + ev.y * ev.y + ev.z * ev.z + ev.w * ev.w;
        atomicAdd(&rsh[row], rq);
        cs[0] += ev.x; cs[1] += ev.y; cs[2] += ev.z; cs[3] += ev.w;
    }
    __syncthreads();
    if (t < 16) g_r[rowbase + t] = rsh[t];
    if (t == 0) {
        float tt = 0.f;
        for (int i = 0; i < 16; i++) tt += rsh[i];
        atomicAdd(&g_T, tt);
    }
    if (final_flag) {
        atomicAdd(&g_sf[c0 + 0], cs[0]);
        atomicAdd(&g_sf[c0 + 1], cs[1]);
        atomicAdd(&g_sf[c0 + 2], cs[2]);
        atomicAdd(&g_sf[c0 + 3], cs[3]);
    }
}

// ---- K6: out[j] = E[j] . sf / N, j < N-1 ----
__global__ void k_out(float* __restrict__ out) {
    int warp = threadIdx.x >> 5, lane = threadIdx.x & 31;
    int row = blockIdx.x * 8 + warp;
    if (row >= NN - 1) return;
    float d = 0.f;
#pragma unroll
    for (int u = 0; u < 8; u++) { int c = lane + 32 * u; d += g_E[row * FF + c] * g_sf[c]; }
#pragma unroll
    for (int o = 16; o > 0; o >>= 1) d += __shfl_xor_sync(0xffffffffu, d, o);
    if (lane == 0) out[row] = d * (1.0f / NN);
}

extern "C" void kernel_launch(void* const* d_in, const int* in_sizes, int n_in,
                              void* d_out, int out_size) {
    const float* X = (const float*)d_in[0];
    // d_in[1] = coefs (unused by the reference forward)
    const float* linear = (const float*)d_in[2];
    const float* dirv   = (const float*)d_in[3];
    const float* feat   = (const float*)d_in[4];
    float* out = (float*)d_out;

    k_ab<<<1, 256>>>(linear, dirv, feat);
    k_zero<<<256, 256>>>(1 | 2 | 4 | 8);           // T, G, s, sf = 0
    k_rownorm<<<1024, 256>>>(X);                    // r(X), T
    k_scale<<<256, 256>>>(X, 0, 0);                 // Y = a0-scale, s += colsum
    k_syrk<<<dim3(16, 16), 256>>>();                // G += Y^T Y
    k_zero<<<1, 32>>>(1);                           // T = 0 (for next iter)
    k_update<<<512, 256>>>(0);                      // E = f(Y,G,s); r(E), T
    k_zero<<<256, 256>>>(2 | 4);                    // G, s = 0
    k_scale<<<256, 256>>>(X, 1, 1);                 // Y = b-scaled E
    k_syrk<<<dim3(16, 16), 256>>>();                // G += Y^T Y
    k_update<<<512, 256>>>(1);                      // final E; sf += colsum(E)
    k_out<<<1024, 256>>>(out);                      // out = E.sf/N
}

// round 2
// speedup vs baseline: 3.5519x; 3.5519x over previous
#include <cuda_runtime.h>
#include <cuda_bf16.h>
#include <cstdint>

#define NN 8192
#define FF 256

// ---- device scratch ----
__device__ __align__(16) float g_E[NN * FF];             // updated emb (fp32)
__device__ __align__(16) __nv_bfloat16 g_Yt[FF * NN];    // Y transposed, bf16 [feature][row]
__device__ __align__(16) float g_Gp[32 * FF * FF];       // SYRK split-K partials
__device__ __align__(16) __nv_bfloat16 g_Gh[FF * FF];    // Gram matrix bf16 [n][k] (symmetric)
__device__ __align__(16) float g_s[FF];                  // colsum(Y)
__device__ __align__(16) float g_sf[FF];                 // colsum(final E)
__device__ float g_r[NN];                                // per-row sumsq
__device__ float g_alpha[NN];                            // per-row scale factor
__device__ float g_d[NN];                                // d_j = Y_j . s
__device__ float g_T;                                    // Frobenius^2
__device__ float g_ab[4];                                // a0,b0,a1,b1

// ---- mma / ldmatrix helpers ----
__device__ __forceinline__ uint32_t smem_u32(const void* p) {
    return (uint32_t)__cvta_generic_to_shared(p);
}
__device__ __forceinline__ void ldsm4(uint32_t (&r)[4], uint32_t addr) {
    asm volatile("ldmatrix.sync.aligned.m8n8.x4.shared.b16 {%0,%1,%2,%3}, [%4];"
                 : "=r"(r[0]), "=r"(r[1]), "=r"(r[2]), "=r"(r[3]) : "r"(addr));
}
__device__ __forceinline__ void ldsm4t(uint32_t (&r)[4], uint32_t addr) {
    asm volatile("ldmatrix.sync.aligned.m8n8.x4.trans.shared.b16 {%0,%1,%2,%3}, [%4];"
                 : "=r"(r[0]), "=r"(r[1]), "=r"(r[2]), "=r"(r[3]) : "r"(addr));
}
__device__ __forceinline__ void mma16816(float* c, const uint32_t* a, uint32_t b0, uint32_t b1) {
    asm volatile("mma.sync.aligned.m16n8k16.row.col.f32.bf16.bf16.f32 "
                 "{%0,%1,%2,%3}, {%4,%5,%6,%7}, {%8,%9}, {%0,%1,%2,%3};"
                 : "+f"(c[0]), "+f"(c[1]), "+f"(c[2]), "+f"(c[3])
                 : "r"(a[0]), "r"(a[1]), "r"(a[2]), "r"(a[3]), "r"(b0), "r"(b1));
}

// ---- K0: a_i = feat_i . linear_i, b_i = dirv_i . linear_i ----
__global__ void k_ab(const float* __restrict__ linear,
                     const float* __restrict__ dirv,
                     const float* __restrict__ feat) {
    __shared__ float red[256];
    int t = threadIdx.x;
    for (int i = 0; i < 2; i++) {
        float pa = feat[i * FF + t] * linear[i * FF + t];
        float pb = dirv[i * FF + t] * linear[i * FF + t];
        red[t] = pa; __syncthreads();
        for (int o = 128; o > 0; o >>= 1) { if (t < o) red[t] += red[t + o]; __syncthreads(); }
        if (t == 0) g_ab[2 * i] = red[0];
        __syncthreads();
        red[t] = pb; __syncthreads();
        for (int o = 128; o > 0; o >>= 1) { if (t < o) red[t] += red[t + o]; __syncthreads(); }
        if (t == 0) g_ab[2 * i + 1] = red[0];
        __syncthreads();
    }
}

// ---- zero selected accumulators: 1=T, 4=s, 8=sf, 16=r ----
__global__ void k_zero(int mode) {
    int i = blockIdx.x * blockDim.x + threadIdx.x;
    if ((mode & 1) && i == 0) g_T = 0.f;
    if ((mode & 4) && i < FF) g_s[i] = 0.f;
    if ((mode & 8) && i < FF) g_sf[i] = 0.f;
    if ((mode & 16) && i < NN) g_r[i] = 0.f;
}

// ---- per-row sumsq of X, accumulate total ----
__global__ void k_rownorm(const float* __restrict__ X) {
    int warp = threadIdx.x >> 5, lane = threadIdx.x & 31;
    int row = blockIdx.x * 8 + warp;
    const float* xr = X + row * FF;
    float s = 0.f;
#pragma unroll
    for (int u = 0; u < 8; u++) { float v = xr[lane + 32 * u]; s += v * v; }
#pragma unroll
    for (int o = 16; o > 0; o >>= 1) s += __shfl_xor_sync(0xffffffffu, s, o);
    __shared__ float ws[8];
    if (lane == 0) { ws[warp] = s; g_r[row] = s; }
    __syncthreads();
    if (threadIdx.x == 0) {
        float tt = 0.f;
        for (int w = 0; w < 8; w++) tt += ws[w];
        atomicAdd(&g_T, tt);
    }
}

// ---- alpha[j] from r[j], T, a, b ----
__global__ void k_alpha(int iter) {
    int j = blockIdx.x * 256 + threadIdx.x;
    float a = g_ab[2 * iter], bb = g_ab[2 * iter + 1];
    float nf = sqrtf(g_T);
    float sb = (bb >= 0.f) ? 1.f : -1.f;
    float inner = a * sb * g_r[j] / nf;
    float scale = (inner <= 0.f) ? inner : 0.f;
    g_alpha[j] = a - scale * sb / nf;
}

// ---- prep: Yt[c][j] = bf16(alpha_j * src[j][c]), fused colsum s ----
__global__ void k_prep(const float* __restrict__ xin, int useE) {
    const float* src = useE ? g_E : xin;
    __shared__ float sh[64][65];
    __shared__ float csm[64];
    int t = threadIdx.x;
    int jt = blockIdx.x >> 2;
    int cb = (blockIdx.x & 3) * 64;
    int j0 = jt * 64;
    if (t < 64) csm[t] = 0.f;
    __syncthreads();
    int lr = t >> 4, lc = (t & 15) * 4;
    float ca0 = 0, ca1 = 0, ca2 = 0, ca3 = 0;
#pragma unroll
    for (int w = 0; w < 4; w++) {
        int row = lr + w * 16;
        int J = j0 + row;
        float al = g_alpha[J];
        float4 v = *(const float4*)&src[J * FF + cb + lc];
        float y0 = al * v.x, y1 = al * v.y, y2 = al * v.z, y3 = al * v.w;
        sh[row][lc] = y0; sh[row][lc + 1] = y1; sh[row][lc + 2] = y2; sh[row][lc + 3] = y3;
        ca0 += y0; ca1 += y1; ca2 += y2; ca3 += y3;
    }
    atomicAdd(&csm[lc], ca0); atomicAdd(&csm[lc + 1], ca1);
    atomicAdd(&csm[lc + 2], ca2); atomicAdd(&csm[lc + 3], ca3);
    __syncthreads();
    int cl = t >> 4, jl = (t & 15) * 4;
#pragma unroll
    for (int w = 0; w < 4; w++) {
        int c = cl + w * 16;
        __nv_bfloat16 p[4];
        p[0] = __float2bfloat16(sh[jl + 0][c]);
        p[1] = __float2bfloat16(sh[jl + 1][c]);
        p[2] = __float2bfloat16(sh[jl + 2][c]);
        p[3] = __float2bfloat16(sh[jl + 3][c]);
        *(uint2*)&g_Yt[(cb + c) * NN + j0 + jl] = *(uint2*)p;
    }
    if (t < 64) atomicAdd(&g_s[cb + t], csm[t]);
}

// ---- SYRK: Gp[chunk] = Yt_tile^T-style product over 256 rows (bf16 mma) ----
__global__ __launch_bounds__(256, 2) void k_syrk() {
    __shared__ __nv_bfloat16 Ash[128][72];
    __shared__ __nv_bfloat16 Bsh[128][72];
    int t = threadIdx.x, lane = t & 31, w = t >> 5;
    int wm = w >> 2, wn = w & 3;          // warps 2x4 -> tile 64x32
    int pa = blockIdx.x >> 1, pb = blockIdx.x & 1;
    int j0 = blockIdx.y * 256;
    float acc[4][4][4];
#pragma unroll
    for (int i = 0; i < 4; i++)
#pragma unroll
        for (int j = 0; j < 4; j++)
#pragma unroll
            for (int q = 0; q < 4; q++) acc[i][j][q] = 0.f;

    for (int ks = 0; ks < 4; ks++) {
        __syncthreads();
#pragma unroll
        for (int u = 0; u < 4; u++) {
            int idx = t + u * 256;
            int row = idx >> 3, g = idx & 7;
            *(uint4*)&Ash[row][g * 8] = *(const uint4*)&g_Yt[(pa * 128 + row) * NN + j0 + ks * 64 + g * 8];
            *(uint4*)&Bsh[row][g * 8] = *(const uint4*)&g_Yt[(pb * 128 + row) * NN + j0 + ks * 64 + g * 8];
        }
        __syncthreads();
#pragma unroll
        for (int kk = 0; kk < 4; kk++) {
            uint32_t a[4][4], b[2][4];
#pragma unroll
            for (int mi = 0; mi < 4; mi++) {
                int row = wm * 64 + mi * 16 + (lane & 15);
                int col = kk * 16 + 8 * (lane >> 4);
                ldsm4(a[mi], smem_u32(&Ash[row][col]));
            }
#pragma unroll
            for (int p = 0; p < 2; p++) {
                int g = lane >> 3;
                int row = wn * 32 + p * 16 + 8 * (g >> 1) + (lane & 7);
                int col = kk * 16 + 8 * (g & 1);
                ldsm4(b[p], smem_u32(&Bsh[row][col]));
            }
#pragma unroll
            for (int mi = 0; mi < 4; mi++)
#pragma unroll
                for (int nj = 0; nj < 4; nj++)
                    mma16816(acc[mi][nj], a[mi], b[nj >> 1][(nj & 1) * 2], b[nj >> 1][(nj & 1) * 2 + 1]);
        }
    }
    float* gp = &g_Gp[blockIdx.y * (FF * FF)];
#pragma unroll
    for (int mi = 0; mi < 4; mi++)
#pragma unroll
        for (int nj = 0; nj < 4; nj++)
#pragma unroll
            for (int gi = 0; gi < 2; gi++) {
                int row = pa * 128 + wm * 64 + mi * 16 + (lane >> 2) + 8 * gi;
                int col = pb * 128 + wn * 32 + nj * 8 + (lane & 3) * 2;
                *(float2*)&gp[row * FF + col] = make_float2(acc[mi][nj][2 * gi], acc[mi][nj][2 * gi + 1]);
            }
}

// ---- reduce SYRK partials -> Gh bf16 ----
__global__ void k_gred() {
    int i = blockIdx.x * 256 + threadIdx.x;
    float s = 0.f;
#pragma unroll
    for (int ch = 0; ch < 32; ch++) s += g_Gp[ch * (FF * FF) + i];
    g_Gh[i] = __float2bfloat16(s);
}

// ---- d[j] = alpha_j * (src_j . s) ----
__global__ void k_dots(const float* __restrict__ xin, int useE) {
    const float* src = useE ? g_E : xin;
    __shared__ float s_sh[FF];
    int t = threadIdx.x;
    s_sh[t] = g_s[t];
    __syncthreads();
    int wp = t >> 5, lane = t & 31;
    int row = blockIdx.x * 8 + wp;
    const float* r = &src[row * FF];
    float d = 0.f;
#pragma unroll
    for (int u = 0; u < 8; u++) { int c = lane + 32 * u; d += r[c] * s_sh[c]; }
#pragma unroll
    for (int o = 16; o > 0; o >>= 1) d += __shfl_xor_sync(0xffffffffu, d, o);
    if (lane == 0) g_d[row] = g_alpha[row] * d;
}

// ---- update: E = y + (Y.Gh - d*y)/N, fused r(E),T, optional colsum sf ----
__global__ __launch_bounds__(256, 2) void k_update(int final_flag, const float* __restrict__ xin, int useE) {
    const float* src = useE ? g_E : xin;
    __shared__ __nv_bfloat16 Ysh[16][136];
    __shared__ __nv_bfloat16 Gsh[128][24];
    __shared__ float rsm[128];
    __shared__ float csm[128];
    int t = threadIdx.x, lane = t & 31, w = t >> 5;
    int wm = w >> 2, wn = w & 3;
    int rt = blockIdx.x >> 1, ct = blockIdx.x & 1;
    int rowbase = rt * 128, colbase = ct * 128;
    if (t < 128) { rsm[t] = 0.f; csm[t] = 0.f; }
    float acc[4][4][4];
#pragma unroll
    for (int i = 0; i < 4; i++)
#pragma unroll
        for (int j = 0; j < 4; j++)
#pragma unroll
            for (int q = 0; q < 4; q++) acc[i][j][q] = 0.f;

    for (int kk = 0; kk < 16; kk++) {
        __syncthreads();
        {
            int row = t >> 4, g = t & 15;
            *(uint4*)&Ysh[row][g * 8] = *(const uint4*)&g_Yt[(kk * 16 + row) * NN + rowbase + g * 8];
        }
        {
            int n = t >> 1, g = t & 1;
            *(uint4*)&Gsh[n][g * 8] = *(const uint4*)&g_Gh[(colbase + n) * FF + kk * 16 + g * 8];
        }
        __syncthreads();
        uint32_t a[4][4], b[2][4];
#pragma unroll
        for (int mi = 0; mi < 4; mi++) {
            int krow = (lane & 7) + 8 * ((lane >> 4) & 1);
            int mcol = wm * 64 + mi * 16 + 8 * ((lane >> 3) & 1);
            ldsm4t(a[mi], smem_u32(&Ysh[krow][mcol]));
        }
#pragma unroll
        for (int p = 0; p < 2; p++) {
            int g = lane >> 3;
            int row = wn * 32 + p * 16 + 8 * (g >> 1) + (lane & 7);
            int col = 8 * (g & 1);
            ldsm4(b[p], smem_u32(&Gsh[row][col]));
        }
#pragma unroll
        for (int mi = 0; mi < 4; mi++)
#pragma unroll
            for (int nj = 0; nj < 4; nj++)
                mma16816(acc[mi][nj], a[mi], b[nj >> 1][(nj & 1) * 2], b[nj >> 1][(nj & 1) * 2 + 1]);
    }

    const float inv = 1.0f / (float)NN;
    float rowsq[4][2];
    float colsm[4][2];
#pragma unroll
    for (int i = 0; i < 4; i++) { rowsq[i][0] = 0.f; rowsq[i][1] = 0.f; colsm[i][0] = 0.f; colsm[i][1] = 0.f; }

#pragma unroll
    for (int mi = 0; mi < 4; mi++)
#pragma unroll
        for (int gi = 0; gi < 2; gi++) {
            int r = wm * 64 + mi * 16 + (lane >> 2) + 8 * gi;
            int Rg = rowbase + r;
            float al = g_alpha[Rg], dd = g_d[Rg];
#pragma unroll
            for (int nj = 0; nj < 4; nj++) {
                int c = colbase + wn * 32 + nj * 8 + (lane & 3) * 2;
                float2 v = *(const float2*)&src[Rg * FF + c];
                float y0 = al * v.x, y1 = al * v.y;
                float e0 = y0 + (acc[mi][nj][2 * gi] - dd * y0) * inv;
                float e1 = y1 + (acc[mi][nj][2 * gi + 1] - dd * y1) * inv;
                *(float2*)&g_E[Rg * FF + c] = make_float2(e0, e1);
                rowsq[mi][gi] += e0 * e0 + e1 * e1;
                colsm[nj][0] += e0; colsm[nj][1] += e1;
            }
        }
#pragma unroll
    for (int mi = 0; mi < 4; mi++)
#pragma unroll
        for (int gi = 0; gi < 2; gi++) {
            float v = rowsq[mi][gi];
            v += __shfl_xor_sync(0xffffffffu, v, 1);
            v += __shfl_xor_sync(0xffffffffu, v, 2);
            if ((lane & 3) == 0) atomicAdd(&rsm[wm * 64 + mi * 16 + (lane >> 2) + 8 * gi], v);
        }
    if (final_flag) {
#pragma unroll
        for (int nj = 0; nj < 4; nj++)
#pragma unroll
            for (int h = 0; h < 2; h++) {
                float v = colsm[nj][h];
                v += __shfl_xor_sync(0xffffffffu, v, 4);
                v += __shfl_xor_sync(0xffffffffu, v, 8);
                v += __shfl_xor_sync(0xffffffffu, v, 16);
                if (lane < 4) atomicAdd(&csm[wn * 32 + nj * 8 + (lane & 3) * 2 + h], v);
            }
    }
    __syncthreads();
    if (t < 128) atomicAdd(&g_r[rowbase + t], rsm[t]);
    if (t == 0) {
        float tt = 0.f;
        for (int i = 0; i < 128; i++) tt += rsm[i];
        atomicAdd(&g_T, tt);
    }
    if (final_flag && t < 128) atomicAdd(&g_sf[colbase + t], csm[t]);
}

// ---- out[j] = E[j] . sf / N ----
__global__ void k_out(float* __restrict__ out) {
    __shared__ float s_sh[FF];
    int t = threadIdx.x;
    s_sh[t] = g_sf[t];
    __syncthreads();
    int warp = t >> 5, lane = t & 31;
    int row = blockIdx.x * 8 + warp;
    if (row >= NN - 1) return;
    float d = 0.f;
#pragma unroll
    for (int u = 0; u < 8; u++) { int c = lane + 32 * u; d += g_E[row * FF + c] * s_sh[c]; }
#pragma unroll
    for (int o = 16; o > 0; o >>= 1) d += __shfl_xor_sync(0xffffffffu, d, o);
    if (lane == 0) out[row] = d * (1.0f / (float)NN);
}

extern "C" void kernel_launch(void* const* d_in, const int* in_sizes, int n_in,
                              void* d_out, int out_size) {
    const float* X      = (const float*)d_in[0];
    const float* linear = (const float*)d_in[2];
    const float* dirv   = (const float*)d_in[3];
    const float* feat   = (const float*)d_in[4];
    float* out = (float*)d_out;

    k_ab<<<1, 256>>>(linear, dirv, feat);
    k_zero<<<32, 256>>>(1 | 4 | 8);          // T, s, sf = 0
    k_rownorm<<<1024, 256>>>(X);             // r(X), T
    k_alpha<<<32, 256>>>(0);                 // alpha from r,T,a0,b0
    k_prep<<<512, 256>>>(X, 0);              // Yt bf16 + s
    k_syrk<<<dim3(4, 32), 256>>>();          // Gp partials
    k_gred<<<256, 256>>>();                  // Gh = reduce(Gp)
    k_dots<<<1024, 256>>>(X, 0);             // d = alpha*(src.s)
    k_zero<<<32, 256>>>(1 | 4 | 16);         // T, s, r = 0 for iter 2
    k_update<<<128, 256>>>(0, X, 0);         // E, r(E), T
    k_alpha<<<32, 256>>>(1);
    k_prep<<<512, 256>>>(X, 1);              // src = E
    k_syrk<<<dim3(4, 32), 256>>>();
    k_gred<<<256, 256>>>();
    k_dots<<<1024, 256>>>(X, 1);
    k_update<<<128, 256>>>(1, X, 1);         // final E (in-place), sf
    k_out<<<1024, 256>>>(out);
}